// round 3
// baseline (speedup 1.0000x reference)
#include <cuda_runtime.h>

#define Dm 128
#define Hm 256
#define ROWS 16384   /* 16 * 1024 chunks */
#define NTOK 131072  /* 16 * 8192 tokens */
#define EPSf 1e-5f

typedef unsigned long long u64;

// ---- scratch (device globals; no allocation) ----
__device__ float g_local[NTOK * Dm];   // 64 MB
__device__ float g_hA[ROWS * Dm];      // 8 MB
__device__ float g_hB[ROWS * Dm];      // 8 MB
__device__ float g_bcb[ROWS * Dm];     // 8 MB

// ---- packed f32x2 helpers ----
__device__ __forceinline__ u64 pk2(float x, float y) {
    u64 r; asm("mov.b64 %0, {%1, %2};" : "=l"(r) : "f"(x), "f"(y)); return r;
}
__device__ __forceinline__ u64 dup_f(float a) {
    u64 r; asm("mov.b64 %0, {%1, %1};" : "=l"(r) : "f"(a)); return r;
}
__device__ __forceinline__ void fma2(u64& d, u64 a, u64 b) {
    asm("fma.rn.f32x2 %0, %1, %2, %0;" : "+l"(d) : "l"(a), "l"(b));
}
__device__ __forceinline__ float2 u2f(u64 v) {
    float2 r; asm("mov.b64 {%0, %1}, %2;" : "=f"(r.x), "=f"(r.y) : "l"(v)); return r;
}

__device__ __forceinline__ float wsum(float v) {
#pragma unroll
    for (int o = 16; o; o >>= 1) v += __shfl_xor_sync(0xffffffffu, v, o);
    return v;
}
__device__ __forceinline__ float gelu_f(float x) { return x * normcdff(x); }

// warp LayerNorm of a 128-wide row held as float4 per lane
__device__ __forceinline__ float4 ln_f4(float4 h, const float* __restrict__ g,
                                        const float* __restrict__ b, int lane) {
    const float mu = wsum(h.x + h.y + h.z + h.w) * (1.0f / 128.0f);
    const float a0 = h.x - mu, a1 = h.y - mu, a2 = h.z - mu, a3 = h.w - mu;
    const float var = wsum(a0 * a0 + a1 * a1 + a2 * a2 + a3 * a3) * (1.0f / 128.0f);
    const float rs = rsqrtf(var + EPSf);
    const int dd = lane * 4;
    const float4 gg = *(const float4*)(g + dd);
    const float4 bb = *(const float4*)(b + dd);
    return make_float4(a0 * rs * gg.x + bb.x, a1 * rs * gg.y + bb.y,
                       a2 * rs * gg.z + bb.z, a3 * rs * gg.w + bb.w);
}

// ---- core register-tiled GEMM accumulate ----
template<int KDIM, int RPT, int NCP>
__device__ __forceinline__ void mm_acc(const float* __restrict__ s,
                                       const float* __restrict__ W, const int ldw,
                                       u64 acc[RPT][NCP]) {
#pragma unroll 2
    for (int d = 0; d < KDIM; d += 2) {
        u64 w0[NCP], w1[NCP];
        if constexpr (NCP >= 2) {
#pragma unroll
            for (int c = 0; c < NCP; c += 2) {
                const ulonglong2 t0 = *(const ulonglong2*)(W + d * ldw + c * 2);
                const ulonglong2 t1 = *(const ulonglong2*)(W + (d + 1) * ldw + c * 2);
                w0[c] = t0.x; w0[c + 1] = t0.y;
                w1[c] = t1.x; w1[c + 1] = t1.y;
            }
        } else {
            w0[0] = *(const u64*)(W + d * ldw);
            w1[0] = *(const u64*)(W + (d + 1) * ldw);
        }
#pragma unroll
        for (int r = 0; r < RPT; ++r) {
            const float2 a = *(const float2*)(s + r * KDIM + d);
            const u64 a0 = dup_f(a.x), a1 = dup_f(a.y);
#pragma unroll
            for (int c = 0; c < NCP; ++c) {
                fma2(acc[r][c], a0, w0[c]);
                fma2(acc[r][c], a1, w1[c]);
            }
        }
    }
}

// ============================================================
// K1: local = h + MLP2(LN(h)); h = emb[x] + pos[t%8]
// + fused pool: summ = mean(local over chunk) @ pool_w + pool_b
// 64 tokens (= 8 chunks) / block, 256 threads, 96KB dyn smem
// ============================================================
__global__ __launch_bounds__(256) void k_local(
    const int* __restrict__ x, const float* __restrict__ emb, const float* __restrict__ pos,
    const float* __restrict__ lw1, const float* __restrict__ lb1,
    const float* __restrict__ lw2, const float* __restrict__ lb2,
    const float* __restrict__ lng, const float* __restrict__ lnb,
    const float* __restrict__ pw, const float* __restrict__ pb)
{
    extern __shared__ float sm[];
    float* s_x = sm;               // 64*128 : xln, then local output
    float* s_h = sm + 64 * 128;    // 64*256 : hidden, then chunk means
    const int tid = threadIdx.x, wq = tid >> 5, lane = tid & 31;
    const int gt0 = blockIdx.x * 64;

    // phase 1: LN per token
#pragma unroll
    for (int tt = 0; tt < 8; ++tt) {
        const int tl = wq * 8 + tt, gt = gt0 + tl;
        const int xt = __ldg(x + gt);
        const float4 e = *(const float4*)(emb + xt * Dm + lane * 4);
        const float4 p = *(const float4*)(pos + (gt & 7) * Dm + lane * 4);
        const float4 h = make_float4(e.x + p.x, e.y + p.y, e.z + p.z, e.w + p.w);
        *(float4*)(s_x + tl * Dm + lane * 4) = ln_f4(h, lng, lnb, lane);
    }
    __syncthreads();

    // phase 2: hid = gelu(xln @ lw1 + b1)  (64 x 256)
    {
        const int j0 = (tid & 31) * 8, rg = tid >> 5;
        u64 acc[8][4];
#pragma unroll
        for (int c = 0; c < 4; ++c) {
            const u64 bp = pk2(lb1[j0 + 2 * c], lb1[j0 + 2 * c + 1]);
#pragma unroll
            for (int r = 0; r < 8; ++r) acc[r][c] = bp;
        }
        mm_acc<128, 8, 4>(s_x + rg * 8 * 128, lw1 + j0, 256, acc);
        __syncthreads();   // s_h about to be overwritten? no: s_h written below; sync for s_x reads done
#pragma unroll
        for (int r = 0; r < 8; ++r) {
            float o[8];
#pragma unroll
            for (int c = 0; c < 4; ++c) {
                const float2 v = u2f(acc[r][c]);
                o[2 * c] = gelu_f(v.x); o[2 * c + 1] = gelu_f(v.y);
            }
            float* dst = s_h + (rg * 8 + r) * 256 + j0;
            *(float4*)dst       = make_float4(o[0], o[1], o[2], o[3]);
            *(float4*)(dst + 4) = make_float4(o[4], o[5], o[6], o[7]);
        }
    }
    __syncthreads();

    // phase 3: out = h + hid @ lw2 + b2 -> g_local and s_x
    {
        const int j0 = (tid & 31) * 4, rg = tid >> 5;
        u64 acc[8][2];
#pragma unroll
        for (int c = 0; c < 2; ++c) {
            const u64 bp = pk2(lb2[j0 + 2 * c], lb2[j0 + 2 * c + 1]);
#pragma unroll
            for (int r = 0; r < 8; ++r) acc[r][c] = bp;
        }
        mm_acc<256, 8, 2>(s_h + rg * 8 * 256, lw2 + j0, 128, acc);
#pragma unroll
        for (int r = 0; r < 8; ++r) {
            const int tl = rg * 8 + r, gt = gt0 + tl;
            const int xt = __ldg(x + gt);
            const float4 e = *(const float4*)(emb + xt * Dm + j0);
            const float4 p = *(const float4*)(pos + (gt & 7) * Dm + j0);
            const float2 v0 = u2f(acc[r][0]), v1 = u2f(acc[r][1]);
            const float4 o = make_float4(e.x + p.x + v0.x, e.y + p.y + v0.y,
                                         e.z + p.z + v1.x, e.w + p.w + v1.y);
            *(float4*)(g_local + gt * Dm + j0) = o;
            *(float4*)(s_x + tl * Dm + j0) = o;
        }
    }
    __syncthreads();

    // phase 4 (fused pool): chunk means -> s_h[0:8*128]
#pragma unroll
    for (int it = 0; it < 4; ++it) {
        const int idx = tid + it * 256;
        const int c = idx >> 7, dd = idx & 127;
        float s = 0.f;
#pragma unroll
        for (int t = 0; t < 8; ++t) s += s_x[(c * 8 + t) * Dm + dd];
        s_h[c * 128 + dd] = s * 0.125f;
    }
    __syncthreads();

    // phase 5: summ = mean @ pool_w + pool_b -> g_hA (8 chunks)
    {
        const int r = tid >> 5, j0 = lane * 4;
        u64 acc1[1][2];
        acc1[0][0] = pk2(pb[j0], pb[j0 + 1]);
        acc1[0][1] = pk2(pb[j0 + 2], pb[j0 + 3]);
        mm_acc<128, 1, 2>(s_h + r * 128, pw + j0, 128, acc1);
        const float2 v0 = u2f(acc1[0][0]), v1 = u2f(acc1[0][1]);
        *(float4*)(g_hA + (blockIdx.x * 8 + r) * Dm + j0) =
            make_float4(v0.x, v0.y, v1.x, v1.y);
    }
}

// ============================================================
// K3: fused proj + msg round. 16 rows/block (+4 halo), 256 thr
// smem 48KB dyn, target 4 CTAs/SM
// ============================================================
__global__ __launch_bounds__(256, 4) void k_msg(
    int useA, const float* __restrict__ mw1,
    const float* __restrict__ mb1, const float* __restrict__ mw2, const float* __restrict__ mb2,
    const float* __restrict__ uw1, const float* __restrict__ ub1,
    const float* __restrict__ uw2, const float* __restrict__ ub2,
    const float* __restrict__ lg, const float* __restrict__ lb)
{
    const float* __restrict__ hin = useA ? g_hA : g_hB;
    float* __restrict__ hout = useA ? g_hB : g_hA;
    extern __shared__ float sm[];
    float* s_hm = sm;               // 24*128 : hmsg rows r0-4 .. r0+15 (v = row-(r0-4)), pad to 24
    float* s_pn = sm + 24 * 128;    // 24*128 : nbr proj (padded)
    float* s_ps = sm + 48 * 128;    // 16*128 : self proj, later uh
    float* s_hs = sm + 64 * 128;    // 16*128 : gelu-sum, later pre-LN
    float* s_ag = sm + 80 * 128;    // 16*128 : agg
    const int tid = threadIdx.x, wq = tid >> 5, lane = tid & 31;
    const int r0 = blockIdx.x * 16;

    // load hmsg rows (clamped)
#pragma unroll
    for (int it = 0; it < 12; ++it) {
        const int idx = tid + it * 256;           // 24*128 = 3072
        const int v = idx >> 7, dd = idx & 127;
        int row = r0 - 4 + v;
        row = row < 0 ? 0 : (row > ROWS - 1 ? ROWS - 1 : row);
        s_hm[idx] = hin[row * Dm + dd];
    }
    __syncthreads();

    const int j0 = lane * 4;

    // self proj: 16 rows (2 rows/warp), cols j0..j0+3 of w1_self
    {
        u64 acc[2][2];
#pragma unroll
        for (int r = 0; r < 2; ++r) { acc[r][0] = 0ull; acc[r][1] = 0ull; }
        mm_acc<128, 2, 2>(s_hm + (4 + wq * 2) * 128, mw1 + j0, 128, acc);
#pragma unroll
        for (int r = 0; r < 2; ++r) {
            const float2 v0 = u2f(acc[r][0]), v1 = u2f(acc[r][1]);
            *(float4*)(s_ps + (wq * 2 + r) * 128 + j0) = make_float4(v0.x, v0.y, v1.x, v1.y);
        }
    }
    // nbr proj: 20 rows padded to 24 (3 rows/warp), cols of w1_nbr
    {
        u64 acc[3][2];
#pragma unroll
        for (int r = 0; r < 3; ++r) { acc[r][0] = 0ull; acc[r][1] = 0ull; }
        mm_acc<128, 3, 2>(s_hm + wq * 3 * 128, mw1 + 128 * 128 + j0, 128, acc);
#pragma unroll
        for (int r = 0; r < 3; ++r) {
            const int v = wq * 3 + r;
            if (v < 20) {
                const float2 v0 = u2f(acc[r][0]), v1 = u2f(acc[r][1]);
                *(float4*)(s_pn + v * 128 + j0) = make_float4(v0.x, v0.y, v1.x, v1.y);
            }
        }
    }
    __syncthreads();

    // phase A: s_hs[r][j] = sum_{dd=0..4, i>=dd} gelu(ps + pn[r-dd+4] + b1)
#pragma unroll
    for (int it = 0; it < 8; ++it) {
        const int idx = tid + it * 256;           // 16*128 = 2048
        const int r = idx >> 7, j = idx & 127;
        const int i = (r0 + r) & 1023;
        const float ps_b = s_ps[r * 128 + j] + mb1[j];
        float a = 0.f;
#pragma unroll
        for (int dd = 0; dd < 5; ++dd) {
            if (i >= dd) a += gelu_f(ps_b + s_pn[(r - dd + 4) * 128 + j]);
        }
        s_hs[r * 128 + j] = a;
    }
    __syncthreads();

    // phase B: agg = hsum @ msg_w2 / count + b2 -> s_ag
    {
        u64 acc[2][2];
#pragma unroll
        for (int r = 0; r < 2; ++r) { acc[r][0] = 0ull; acc[r][1] = 0ull; }
        mm_acc<128, 2, 2>(s_hs + wq * 2 * 128, mw2 + j0, 128, acc);
        const float4 b2 = *(const float4*)(mb2 + j0);
#pragma unroll
        for (int r = 0; r < 2; ++r) {
            const int i = (r0 + wq * 2 + r) & 1023;
            const float inv = 1.0f / ((i + 1) < 5 ? (float)(i + 1) : 5.0f);
            const float2 v0 = u2f(acc[r][0]), v1 = u2f(acc[r][1]);
            *(float4*)(s_ag + (wq * 2 + r) * 128 + j0) =
                make_float4(v0.x * inv + b2.x, v0.y * inv + b2.y,
                            v1.x * inv + b2.z, v1.y * inv + b2.w);
        }
    }
    __syncthreads();

    // phase C: uh = gelu([hmsg, agg] @ upd_w1 + ub1) -> s_ps (reuse)
    {
        u64 acc[2][2];
        acc[0][0] = acc[1][0] = pk2(ub1[j0], ub1[j0 + 1]);
        acc[0][1] = acc[1][1] = pk2(ub1[j0 + 2], ub1[j0 + 3]);
        mm_acc<128, 2, 2>(s_hm + (4 + wq * 2) * 128, uw1 + j0, 128, acc);
        mm_acc<128, 2, 2>(s_ag + wq * 2 * 128, uw1 + 128 * 128 + j0, 128, acc);
        __syncthreads();
#pragma unroll
        for (int r = 0; r < 2; ++r) {
            const float2 v0 = u2f(acc[r][0]), v1 = u2f(acc[r][1]);
            *(float4*)(s_ps + (wq * 2 + r) * 128 + j0) =
                make_float4(gelu_f(v0.x), gelu_f(v0.y), gelu_f(v1.x), gelu_f(v1.y));
        }
    }
    __syncthreads();

    // phase D: pre-LN = hmsg + uh @ upd_w2 + ub2 -> s_hs (reuse)
    {
        u64 acc[2][2];
        acc[0][0] = acc[1][0] = pk2(ub2[j0], ub2[j0 + 1]);
        acc[0][1] = acc[1][1] = pk2(ub2[j0 + 2], ub2[j0 + 3]);
        mm_acc<128, 2, 2>(s_ps + wq * 2 * 128, uw2 + j0, 128, acc);
        __syncthreads();
#pragma unroll
        for (int r = 0; r < 2; ++r) {
            const float2 v0 = u2f(acc[r][0]), v1 = u2f(acc[r][1]);
            const float4 hm = *(const float4*)(s_hm + (4 + wq * 2 + r) * 128 + j0);
            *(float4*)(s_hs + (wq * 2 + r) * 128 + j0) =
                make_float4(hm.x + v0.x, hm.y + v0.y, hm.z + v1.x, hm.w + v1.y);
        }
    }
    __syncthreads();

    // phase E: LN per row (8 warps x 2 rows)
#pragma unroll
    for (int rr = 0; rr < 2; ++rr) {
        const int r = wq * 2 + rr;
        const float4 v = *(const float4*)(s_hs + r * 128 + lane * 4);
        *(float4*)(hout + (r0 + r) * Dm + lane * 4) = ln_f4(v, lg, lb, lane);
    }
}

// ============================================================
// K4: bc = hmsg_final @ bc_w + bc_b  (final state in g_hB)
// ============================================================
__global__ __launch_bounds__(256) void k_bc(
    const float* __restrict__ w, const float* __restrict__ b)
{
    __shared__ float s_r[32 * 128];
    const int tid = threadIdx.x;
    const int r0 = blockIdx.x * 32;
#pragma unroll
    for (int it = 0; it < 16; ++it) {
        const int idx = tid + it * 256;
        s_r[idx] = g_hB[r0 * Dm + idx];
    }
    __syncthreads();
    const int j0 = (tid & 31) * 4, rg = tid >> 5;
    u64 acc[4][2];
#pragma unroll
    for (int c = 0; c < 2; ++c) {
        const u64 bp = pk2(b[j0 + 2 * c], b[j0 + 2 * c + 1]);
#pragma unroll
        for (int r = 0; r < 4; ++r) acc[r][c] = bp;
    }
    mm_acc<128, 4, 2>(s_r + rg * 4 * 128, w + j0, 128, acc);
#pragma unroll
    for (int r = 0; r < 4; ++r) {
        const float2 v0 = u2f(acc[r][0]), v1 = u2f(acc[r][1]);
        *(float4*)(g_bcb + (r0 + rg * 4 + r) * Dm + j0) = make_float4(v0.x, v0.y, v1.x, v1.y);
    }
}

// ============================================================
// K5: logits = LN(local + bc) @ head_w  (64 tokens / block)
// ============================================================
__global__ __launch_bounds__(256) void k_head(
    const float* __restrict__ lg, const float* __restrict__ lb,
    const float* __restrict__ hw, float* __restrict__ out)
{
    __shared__ float s_x[64 * 128];
    const int tid = threadIdx.x, wq = tid >> 5, lane = tid & 31;
    const int gt0 = blockIdx.x * 64;

#pragma unroll
    for (int tt = 0; tt < 8; ++tt) {
        const int tl = wq * 8 + tt, gt = gt0 + tl;
        const float4 lv = *(const float4*)(g_local + gt * Dm + lane * 4);
        const float4 bv = *(const float4*)(g_bcb + (gt >> 3) * Dm + lane * 4);
        const float4 h = make_float4(lv.x + bv.x, lv.y + bv.y, lv.z + bv.z, lv.w + bv.w);
        *(float4*)(s_x + tl * 128 + lane * 4) = ln_f4(h, lg, lb, lane);
    }
    __syncthreads();

    const int j0 = (tid & 31) * 8, rg = tid >> 5;
    u64 acc[8][4];
#pragma unroll
    for (int r = 0; r < 8; ++r)
#pragma unroll
        for (int c = 0; c < 4; ++c) acc[r][c] = 0ull;
    mm_acc<128, 8, 4>(s_x + rg * 8 * 128, hw + j0, 256, acc);
#pragma unroll
    for (int r = 0; r < 8; ++r) {
        float* dst = out + (gt0 + rg * 8 + r) * Hm + j0;
        const float2 v0 = u2f(acc[r][0]), v1 = u2f(acc[r][1]);
        const float2 v2 = u2f(acc[r][2]), v3 = u2f(acc[r][3]);
        *(float4*)dst       = make_float4(v0.x, v0.y, v1.x, v1.y);
        *(float4*)(dst + 4) = make_float4(v2.x, v2.y, v3.x, v3.y);
    }
}

// ============================================================
extern "C" void kernel_launch(void* const* d_in, const int* in_sizes, int n_in,
                              void* d_out, int out_size) {
    const int*   x      = (const int*)  d_in[0];
    const float* emb    = (const float*)d_in[1];
    const float* pos    = (const float*)d_in[2];
    const float* lw1    = (const float*)d_in[3];
    const float* lb1    = (const float*)d_in[4];
    const float* lw2    = (const float*)d_in[5];
    const float* lb2    = (const float*)d_in[6];
    const float* lln_g  = (const float*)d_in[7];
    const float* lln_b  = (const float*)d_in[8];
    const float* pool_w = (const float*)d_in[9];
    const float* pool_b = (const float*)d_in[10];
    const float* msg_w1 = (const float*)d_in[11];
    const float* msg_b1 = (const float*)d_in[12];
    const float* msg_w2 = (const float*)d_in[13];
    const float* msg_b2 = (const float*)d_in[14];
    const float* upd_w1 = (const float*)d_in[15];
    const float* upd_b1 = (const float*)d_in[16];
    const float* upd_w2 = (const float*)d_in[17];
    const float* upd_b2 = (const float*)d_in[18];
    const float* mln_g  = (const float*)d_in[19];
    const float* mln_b  = (const float*)d_in[20];
    const float* bc_w   = (const float*)d_in[21];
    const float* bc_b   = (const float*)d_in[22];
    const float* fln_g  = (const float*)d_in[23];
    const float* fln_b  = (const float*)d_in[24];
    const float* head_w = (const float*)d_in[25];
    float* out = (float*)d_out;

    const int SMEM_LOCAL = 96 * 1024;
    const int SMEM_MSG   = 48 * 1024;
    cudaFuncSetAttribute(k_local, cudaFuncAttributeMaxDynamicSharedMemorySize, SMEM_LOCAL);
    cudaFuncSetAttribute(k_msg,   cudaFuncAttributeMaxDynamicSharedMemorySize, SMEM_MSG);

    k_local<<<NTOK / 64, 256, SMEM_LOCAL>>>(x, emb, pos, lw1, lb1, lw2, lb2,
                                            lln_g, lln_b, pool_w, pool_b);

    // rounds: A->B, B->A, A->B  (final state in g_hB)
    for (int r = 0; r < 3; ++r) {
        const int useA = (r % 2 == 0) ? 1 : 0;
        k_msg<<<ROWS / 16, 256, SMEM_MSG>>>(useA, msg_w1, msg_b1, msg_w2, msg_b2,
                                            upd_w1, upd_b1, upd_w2, upd_b2, mln_g, mln_b);
    }

    k_bc<<<ROWS / 32, 256>>>(bc_w, bc_b);
    k_head<<<NTOK / 64, 256>>>(fln_g, fln_b, head_w, out);
}

// round 4
// speedup vs baseline: 1.6746x; 1.6746x over previous
#include <cuda_runtime.h>

#define Dm 128
#define Hm 256
#define ROWS 16384   /* 16 * 1024 chunks */
#define NTOK 131072  /* 16 * 8192 tokens */
#define EPSf 1e-5f

typedef unsigned long long u64;
typedef unsigned int u32;

// ---- scratch (device globals; no allocation) ----
__device__ float g_local[NTOK * Dm];   // 64 MB
__device__ float g_hA[ROWS * Dm];      // 8 MB
__device__ float g_hB[ROWS * Dm];      // 8 MB
__device__ float g_bcb[ROWS * Dm];     // 8 MB
// packed tf32 weight fragments (frag-order, see k_pack)
__device__ float2 g_w1p[16 * 32 * 32]; // lw1 128x256
__device__ float2 g_w2p[32 * 16 * 32]; // lw2 256x128
__device__ float2 g_hwp[16 * 32 * 32]; // head_w 128x256

// ---- packed f32x2 helpers (scalar path) ----
__device__ __forceinline__ u64 pk2(float x, float y) {
    u64 r; asm("mov.b64 %0, {%1, %2};" : "=l"(r) : "f"(x), "f"(y)); return r;
}
__device__ __forceinline__ u64 dup_f(float a) {
    u64 r; asm("mov.b64 %0, {%1, %1};" : "=l"(r) : "f"(a)); return r;
}
__device__ __forceinline__ void fma2(u64& d, u64 a, u64 b) {
    asm("fma.rn.f32x2 %0, %1, %2, %0;" : "+l"(d) : "l"(a), "l"(b));
}
__device__ __forceinline__ float2 u2f(u64 v) {
    float2 r; asm("mov.b64 {%0, %1}, %2;" : "=f"(r.x), "=f"(r.y) : "l"(v)); return r;
}

// ---- tf32 helpers ----
__device__ __forceinline__ u32 f2tf(float f) {
    u32 r; asm("cvt.rna.tf32.f32 %0, %1;" : "=r"(r) : "f"(f)); return r;
}
__device__ __forceinline__ float f2tff(float f) { return __uint_as_float(f2tf(f)); }

// mma.sync m16n8k8 tf32: D = A(16x8,row) * B(8x8,col) + D
__device__ __forceinline__ void mma8(float4& c, const u32 a[4], u32 b0, u32 b1) {
    asm volatile(
        "mma.sync.aligned.m16n8k8.row.col.f32.tf32.tf32.f32 "
        "{%0,%1,%2,%3}, {%4,%5,%6,%7}, {%8,%9}, {%0,%1,%2,%3};"
        : "+f"(c.x), "+f"(c.y), "+f"(c.z), "+f"(c.w)
        : "r"(a[0]), "r"(a[1]), "r"(a[2]), "r"(a[3]), "r"(b0), "r"(b1));
}

__device__ __forceinline__ float wsum(float v) {
#pragma unroll
    for (int o = 16; o; o >>= 1) v += __shfl_xor_sync(0xffffffffu, v, o);
    return v;
}
__device__ __forceinline__ float gelu_f(float x) { return x * normcdff(x); }

// warp LayerNorm of a 128-wide row held as float4 per lane
__device__ __forceinline__ float4 ln_f4(float4 h, const float* __restrict__ g,
                                        const float* __restrict__ b, int lane) {
    const float mu = wsum(h.x + h.y + h.z + h.w) * (1.0f / 128.0f);
    const float a0 = h.x - mu, a1 = h.y - mu, a2 = h.z - mu, a3 = h.w - mu;
    const float var = wsum(a0 * a0 + a1 * a1 + a2 * a2 + a3 * a3) * (1.0f / 128.0f);
    const float rs = rsqrtf(var + EPSf);
    const int dd = lane * 4;
    const float4 gg = *(const float4*)(g + dd);
    const float4 bb = *(const float4*)(b + dd);
    return make_float4(a0 * rs * gg.x + bb.x, a1 * rs * gg.y + bb.y,
                       a2 * rs * gg.z + bb.z, a3 * rs * gg.w + bb.w);
}

// ---- core register-tiled GEMM accumulate (scalar fma2 path) ----
template<int KDIM, int RPT, int NCP>
__device__ __forceinline__ void mm_acc(const float* __restrict__ s,
                                       const float* __restrict__ W, const int ldw,
                                       u64 acc[RPT][NCP]) {
#pragma unroll 2
    for (int d = 0; d < KDIM; d += 2) {
        u64 w0[NCP], w1[NCP];
        if constexpr (NCP >= 2) {
#pragma unroll
            for (int c = 0; c < NCP; c += 2) {
                const ulonglong2 t0 = *(const ulonglong2*)(W + d * ldw + c * 2);
                const ulonglong2 t1 = *(const ulonglong2*)(W + (d + 1) * ldw + c * 2);
                w0[c] = t0.x; w0[c + 1] = t0.y;
                w1[c] = t1.x; w1[c + 1] = t1.y;
            }
        } else {
            w0[0] = *(const u64*)(W + d * ldw);
            w1[0] = *(const u64*)(W + (d + 1) * ldw);
        }
#pragma unroll
        for (int r = 0; r < RPT; ++r) {
            const float2 a = *(const float2*)(s + r * KDIM + d);
            const u64 a0 = dup_f(a.x), a1 = dup_f(a.y);
#pragma unroll
            for (int c = 0; c < NCP; ++c) {
                fma2(acc[r][c], a0, w0[c]);
                fma2(acc[r][c], a1, w1[c]);
            }
        }
    }
}

// ============================================================
// K0: pack W[K][N] (row-major) into tf32 B-fragment order:
// P[(ks*(N/8)+nt)*32+lane] = { tf32(W[ks*8+lane%4][nt*8+lane/4]),
//                              tf32(W[ks*8+4+lane%4][nt*8+lane/4]) }
// ============================================================
__global__ __launch_bounds__(256) void k_pack(const float* __restrict__ W,
                                              float2* __restrict__ P,
                                              int K, int N) {
    const int idx = blockIdx.x * 256 + threadIdx.x;
    const int total = (K / 8) * (N / 8) * 32;
    if (idx >= total) return;
    const int lane = idx & 31;
    const int t = idx >> 5;
    const int nt = t % (N / 8);
    const int ks = t / (N / 8);
    const int k = ks * 8 + (lane & 3);
    const int n = nt * 8 + (lane >> 2);
    P[idx] = make_float2(f2tff(W[k * N + n]), f2tff(W[(k + 4) * N + n]));
}

// ============================================================
// K1: local = h + MLP2(LN(h)) + fused pool/summ  (tensor-core)
// 128 tokens (=16 chunks)/block, 512 threads, ~196KB dyn smem
// ============================================================
#define SXL 132   /* s_x row stride */
#define SHL 260   /* s_h row stride */
__global__ __launch_bounds__(512) void k_local(
    const int* __restrict__ x, const float* __restrict__ emb, const float* __restrict__ pos,
    const float* __restrict__ lb1, const float* __restrict__ lb2,
    const float* __restrict__ lng, const float* __restrict__ lnb,
    const float* __restrict__ pw, const float* __restrict__ pb)
{
    extern __shared__ float sm[];
    float* s_x = sm;                 // 128 x 132 : tf32 LN, later fp32 local
    float* s_h = sm + 128 * SXL;     // 128 x 260 : tf32 hidden, later chunk means
    const int tid = threadIdx.x, wid = tid >> 5, lane = tid & 31;
    const int gt0 = blockIdx.x * 128;
    const int frow = lane >> 2, fcol = lane & 3;

    // phase 1: LN per token -> tf32 in s_x
#pragma unroll
    for (int tt = 0; tt < 8; ++tt) {
        const int tl = wid * 8 + tt, gt = gt0 + tl;
        const int xt = __ldg(x + gt);
        const float4 e = *(const float4*)(emb + xt * Dm + lane * 4);
        const float4 p = *(const float4*)(pos + (gt & 7) * Dm + lane * 4);
        const float4 h = make_float4(e.x + p.x, e.y + p.y, e.z + p.z, e.w + p.w);
        const float4 v = ln_f4(h, lng, lnb, lane);
        float* dst = s_x + tl * SXL + lane * 4;
        dst[0] = f2tff(v.x); dst[1] = f2tff(v.y); dst[2] = f2tff(v.z); dst[3] = f2tff(v.w);
    }
    __syncthreads();

    const int mg = (wid >> 2) * 32;      // 4 m-groups of 32 rows
    const int ng = (wid & 3);            // 4 n-groups

    // phase 2: hid = gelu(xln @ lw1 + b1) -> tf32 in s_h  (N cols ng*64..+63)
    {
        float4 acc[2][8];
#pragma unroll
        for (int nt = 0; nt < 8; ++nt) {
            const int gc = ng * 64 + nt * 8 + 2 * fcol;
            const float b0 = lb1[gc], b1v = lb1[gc + 1];
#pragma unroll
            for (int mt = 0; mt < 2; ++mt) acc[mt][nt] = make_float4(b0, b1v, b0, b1v);
        }
#pragma unroll 4
        for (int ks = 0; ks < 16; ++ks) {
            u32 a[2][4];
#pragma unroll
            for (int mt = 0; mt < 2; ++mt) {
                const float* ap = s_x + (mg + mt * 16 + frow) * SXL + ks * 8 + fcol;
                a[mt][0] = __float_as_uint(ap[0]);
                a[mt][1] = __float_as_uint(ap[8 * SXL]);
                a[mt][2] = __float_as_uint(ap[4]);
                a[mt][3] = __float_as_uint(ap[8 * SXL + 4]);
            }
#pragma unroll
            for (int nt = 0; nt < 8; ++nt) {
                const float2 b = g_w1p[(ks * 32 + ng * 8 + nt) * 32 + lane];
#pragma unroll
                for (int mt = 0; mt < 2; ++mt)
                    mma8(acc[mt][nt], a[mt], __float_as_uint(b.x), __float_as_uint(b.y));
            }
        }
#pragma unroll
        for (int mt = 0; mt < 2; ++mt) {
            const int rg = mg + mt * 16 + frow;
#pragma unroll
            for (int nt = 0; nt < 8; ++nt) {
                const int gc = ng * 64 + nt * 8 + 2 * fcol;
                *(float2*)(s_h + rg * SHL + gc) =
                    make_float2(f2tff(gelu_f(acc[mt][nt].x)), f2tff(gelu_f(acc[mt][nt].y)));
                *(float2*)(s_h + (rg + 8) * SHL + gc) =
                    make_float2(f2tff(gelu_f(acc[mt][nt].z)), f2tff(gelu_f(acc[mt][nt].w)));
            }
        }
    }
    __syncthreads();

    // phase 3: local = h + hid @ lw2 + b2 -> g_local and s_x (fp32)
    {
        float4 acc[2][4];
#pragma unroll
        for (int nt = 0; nt < 4; ++nt) {
            const int gc = ng * 32 + nt * 8 + 2 * fcol;
            const float b0 = lb2[gc], b1v = lb2[gc + 1];
#pragma unroll
            for (int mt = 0; mt < 2; ++mt) acc[mt][nt] = make_float4(b0, b1v, b0, b1v);
        }
#pragma unroll 4
        for (int ks = 0; ks < 32; ++ks) {
            u32 a[2][4];
#pragma unroll
            for (int mt = 0; mt < 2; ++mt) {
                const float* ap = s_h + (mg + mt * 16 + frow) * SHL + ks * 8 + fcol;
                a[mt][0] = __float_as_uint(ap[0]);
                a[mt][1] = __float_as_uint(ap[8 * SHL]);
                a[mt][2] = __float_as_uint(ap[4]);
                a[mt][3] = __float_as_uint(ap[8 * SHL + 4]);
            }
#pragma unroll
            for (int nt = 0; nt < 4; ++nt) {
                const float2 b = g_w2p[(ks * 16 + ng * 4 + nt) * 32 + lane];
#pragma unroll
                for (int mt = 0; mt < 2; ++mt)
                    mma8(acc[mt][nt], a[mt], __float_as_uint(b.x), __float_as_uint(b.y));
            }
        }
#pragma unroll
        for (int mt = 0; mt < 2; ++mt) {
#pragma unroll
            for (int rr = 0; rr < 2; ++rr) {
                const int tl = mg + mt * 16 + frow + rr * 8;
                const int gt = gt0 + tl;
                const int xt = __ldg(x + gt);
#pragma unroll
                for (int nt = 0; nt < 4; ++nt) {
                    const int gc = ng * 32 + nt * 8 + 2 * fcol;
                    const float2 e = *(const float2*)(emb + xt * Dm + gc);
                    const float2 p = *(const float2*)(pos + (gt & 7) * Dm + gc);
                    const float cx = rr ? acc[mt][nt].z : acc[mt][nt].x;
                    const float cy = rr ? acc[mt][nt].w : acc[mt][nt].y;
                    const float2 o = make_float2(e.x + p.x + cx, e.y + p.y + cy);
                    *(float2*)(g_local + gt * Dm + gc) = o;
                    *(float2*)(s_x + tl * SXL + gc) = o;
                }
            }
        }
    }
    __syncthreads();

    // phase 4: chunk means (16 chunks) -> s_h[0:2048]
#pragma unroll
    for (int it = 0; it < 4; ++it) {
        const int idx = tid + it * 512;
        const int c = idx >> 7, dd = idx & 127;
        float s = 0.f;
#pragma unroll
        for (int t = 0; t < 8; ++t) s += s_x[(c * 8 + t) * SXL + dd];
        s_h[c * 128 + dd] = s * 0.125f;
    }
    __syncthreads();

    // phase 5: summ = mean @ pool_w + pool_b -> g_hA (warp per chunk)
    {
        const int j0 = lane * 4;
        u64 acc1[1][2];
        acc1[0][0] = pk2(pb[j0], pb[j0 + 1]);
        acc1[0][1] = pk2(pb[j0 + 2], pb[j0 + 3]);
        mm_acc<128, 1, 2>(s_h + wid * 128, pw + j0, 128, acc1);
        const float2 v0 = u2f(acc1[0][0]), v1 = u2f(acc1[0][1]);
        *(float4*)(g_hA + (blockIdx.x * 16 + wid) * Dm + j0) =
            make_float4(v0.x, v0.y, v1.x, v1.y);
    }
}

// ============================================================
// K3: fused proj + msg round. 16 rows/block (+4 halo), 256 thr
// ============================================================
__global__ __launch_bounds__(256, 4) void k_msg(
    int useA, const float* __restrict__ mw1,
    const float* __restrict__ mb1, const float* __restrict__ mw2, const float* __restrict__ mb2,
    const float* __restrict__ uw1, const float* __restrict__ ub1,
    const float* __restrict__ uw2, const float* __restrict__ ub2,
    const float* __restrict__ lg, const float* __restrict__ lb)
{
    const float* __restrict__ hin = useA ? g_hA : g_hB;
    float* __restrict__ hout = useA ? g_hB : g_hA;
    extern __shared__ float sm[];
    float* s_hm = sm;               // 24*128
    float* s_pn = sm + 24 * 128;    // 24*128
    float* s_ps = sm + 48 * 128;    // 16*128
    float* s_hs = sm + 64 * 128;    // 16*128
    float* s_ag = sm + 80 * 128;    // 16*128
    const int tid = threadIdx.x, wq = tid >> 5, lane = tid & 31;
    const int r0 = blockIdx.x * 16;

#pragma unroll
    for (int it = 0; it < 12; ++it) {
        const int idx = tid + it * 256;
        const int v = idx >> 7, dd = idx & 127;
        int row = r0 - 4 + v;
        row = row < 0 ? 0 : (row > ROWS - 1 ? ROWS - 1 : row);
        s_hm[idx] = hin[row * Dm + dd];
    }
    __syncthreads();

    const int j0 = lane * 4;

    {
        u64 acc[2][2];
#pragma unroll
        for (int r = 0; r < 2; ++r) { acc[r][0] = 0ull; acc[r][1] = 0ull; }
        mm_acc<128, 2, 2>(s_hm + (4 + wq * 2) * 128, mw1 + j0, 128, acc);
#pragma unroll
        for (int r = 0; r < 2; ++r) {
            const float2 v0 = u2f(acc[r][0]), v1 = u2f(acc[r][1]);
            *(float4*)(s_ps + (wq * 2 + r) * 128 + j0) = make_float4(v0.x, v0.y, v1.x, v1.y);
        }
    }
    {
        u64 acc[3][2];
#pragma unroll
        for (int r = 0; r < 3; ++r) { acc[r][0] = 0ull; acc[r][1] = 0ull; }
        mm_acc<128, 3, 2>(s_hm + wq * 3 * 128, mw1 + 128 * 128 + j0, 128, acc);
#pragma unroll
        for (int r = 0; r < 3; ++r) {
            const int v = wq * 3 + r;
            if (v < 20) {
                const float2 v0 = u2f(acc[r][0]), v1 = u2f(acc[r][1]);
                *(float4*)(s_pn + v * 128 + j0) = make_float4(v0.x, v0.y, v1.x, v1.y);
            }
        }
    }
    __syncthreads();

#pragma unroll
    for (int it = 0; it < 8; ++it) {
        const int idx = tid + it * 256;
        const int r = idx >> 7, j = idx & 127;
        const int i = (r0 + r) & 1023;
        const float ps_b = s_ps[r * 128 + j] + mb1[j];
        float a = 0.f;
#pragma unroll
        for (int dd = 0; dd < 5; ++dd) {
            if (i >= dd) a += gelu_f(ps_b + s_pn[(r - dd + 4) * 128 + j]);
        }
        s_hs[r * 128 + j] = a;
    }
    __syncthreads();

    {
        u64 acc[2][2];
#pragma unroll
        for (int r = 0; r < 2; ++r) { acc[r][0] = 0ull; acc[r][1] = 0ull; }
        mm_acc<128, 2, 2>(s_hs + wq * 2 * 128, mw2 + j0, 128, acc);
        const float4 b2 = *(const float4*)(mb2 + j0);
#pragma unroll
        for (int r = 0; r < 2; ++r) {
            const int i = (r0 + wq * 2 + r) & 1023;
            const float inv = 1.0f / ((i + 1) < 5 ? (float)(i + 1) : 5.0f);
            const float2 v0 = u2f(acc[r][0]), v1 = u2f(acc[r][1]);
            *(float4*)(s_ag + (wq * 2 + r) * 128 + j0) =
                make_float4(v0.x * inv + b2.x, v0.y * inv + b2.y,
                            v1.x * inv + b2.z, v1.y * inv + b2.w);
        }
    }
    __syncthreads();

    {
        u64 acc[2][2];
        acc[0][0] = acc[1][0] = pk2(ub1[j0], ub1[j0 + 1]);
        acc[0][1] = acc[1][1] = pk2(ub1[j0 + 2], ub1[j0 + 3]);
        mm_acc<128, 2, 2>(s_hm + (4 + wq * 2) * 128, uw1 + j0, 128, acc);
        mm_acc<128, 2, 2>(s_ag + wq * 2 * 128, uw1 + 128 * 128 + j0, 128, acc);
        __syncthreads();
#pragma unroll
        for (int r = 0; r < 2; ++r) {
            const float2 v0 = u2f(acc[r][0]), v1 = u2f(acc[r][1]);
            *(float4*)(s_ps + (wq * 2 + r) * 128 + j0) =
                make_float4(gelu_f(v0.x), gelu_f(v0.y), gelu_f(v1.x), gelu_f(v1.y));
        }
    }
    __syncthreads();

    {
        u64 acc[2][2];
        acc[0][0] = acc[1][0] = pk2(ub2[j0], ub2[j0 + 1]);
        acc[0][1] = acc[1][1] = pk2(ub2[j0 + 2], ub2[j0 + 3]);
        mm_acc<128, 2, 2>(s_ps + wq * 2 * 128, uw2 + j0, 128, acc);
        __syncthreads();
#pragma unroll
        for (int r = 0; r < 2; ++r) {
            const float2 v0 = u2f(acc[r][0]), v1 = u2f(acc[r][1]);
            const float4 hm = *(const float4*)(s_hm + (4 + wq * 2 + r) * 128 + j0);
            *(float4*)(s_hs + (wq * 2 + r) * 128 + j0) =
                make_float4(hm.x + v0.x, hm.y + v0.y, hm.z + v1.x, hm.w + v1.y);
        }
    }
    __syncthreads();

#pragma unroll
    for (int rr = 0; rr < 2; ++rr) {
        const int r = wq * 2 + rr;
        const float4 v = *(const float4*)(s_hs + r * 128 + lane * 4);
        *(float4*)(hout + (r0 + r) * Dm + lane * 4) = ln_f4(v, lg, lb, lane);
    }
}

// ============================================================
// K4: bc = hmsg_final @ bc_w + bc_b  (final state in g_hB)
// ============================================================
__global__ __launch_bounds__(256) void k_bc(
    const float* __restrict__ w, const float* __restrict__ b)
{
    __shared__ float s_r[32 * 128];
    const int tid = threadIdx.x;
    const int r0 = blockIdx.x * 32;
#pragma unroll
    for (int it = 0; it < 16; ++it) {
        const int idx = tid + it * 256;
        s_r[idx] = g_hB[r0 * Dm + idx];
    }
    __syncthreads();
    const int j0 = (tid & 31) * 4, rg = tid >> 5;
    u64 acc[4][2];
#pragma unroll
    for (int c = 0; c < 2; ++c) {
        const u64 bp = pk2(b[j0 + 2 * c], b[j0 + 2 * c + 1]);
#pragma unroll
        for (int r = 0; r < 4; ++r) acc[r][c] = bp;
    }
    mm_acc<128, 4, 2>(s_r + rg * 4 * 128, w + j0, 128, acc);
#pragma unroll
    for (int r = 0; r < 4; ++r) {
        const float2 v0 = u2f(acc[r][0]), v1 = u2f(acc[r][1]);
        *(float4*)(g_bcb + (r0 + rg * 4 + r) * Dm + j0) = make_float4(v0.x, v0.y, v1.x, v1.y);
    }
}

// ============================================================
// K5: logits = LN(local + bc) @ head_w  (tensor-core)
// 64 tokens / block, 256 threads
// ============================================================
__global__ __launch_bounds__(256) void k_head(
    const float* __restrict__ lg, const float* __restrict__ lb,
    float* __restrict__ out)
{
    __shared__ float s_x[64 * SXL];
    const int tid = threadIdx.x, wid = tid >> 5, lane = tid & 31;
    const int gt0 = blockIdx.x * 64;
    const int frow = lane >> 2, fcol = lane & 3;

#pragma unroll
    for (int tt = 0; tt < 8; ++tt) {
        const int tl = wid * 8 + tt, gt = gt0 + tl;
        const float4 lv = *(const float4*)(g_local + gt * Dm + lane * 4);
        const float4 bv = *(const float4*)(g_bcb + (gt >> 3) * Dm + lane * 4);
        const float4 h = make_float4(lv.x + bv.x, lv.y + bv.y, lv.z + bv.z, lv.w + bv.w);
        const float4 v = ln_f4(h, lg, lb, lane);
        float* dst = s_x + tl * SXL + lane * 4;
        dst[0] = f2tff(v.x); dst[1] = f2tff(v.y); dst[2] = f2tff(v.z); dst[3] = f2tff(v.w);
    }
    __syncthreads();

    const int mg = (wid >> 2) * 32;   // 2 m-groups of 32 rows
    const int ng = (wid & 3);         // 4 n-groups of 64 cols
    float4 acc[2][8];
#pragma unroll
    for (int mt = 0; mt < 2; ++mt)
#pragma unroll
        for (int nt = 0; nt < 8; ++nt) acc[mt][nt] = make_float4(0.f, 0.f, 0.f, 0.f);

#pragma unroll 4
    for (int ks = 0; ks < 16; ++ks) {
        u32 a[2][4];
#pragma unroll
        for (int mt = 0; mt < 2; ++mt) {
            const float* ap = s_x + (mg + mt * 16 + frow) * SXL + ks * 8 + fcol;
            a[mt][0] = __float_as_uint(ap[0]);
            a[mt][1] = __float_as_uint(ap[8 * SXL]);
            a[mt][2] = __float_as_uint(ap[4]);
            a[mt][3] = __float_as_uint(ap[8 * SXL + 4]);
        }
#pragma unroll
        for (int nt = 0; nt < 8; ++nt) {
            const float2 b = g_hwp[(ks * 32 + ng * 8 + nt) * 32 + lane];
#pragma unroll
            for (int mt = 0; mt < 2; ++mt)
                mma8(acc[mt][nt], a[mt], __float_as_uint(b.x), __float_as_uint(b.y));
        }
    }

#pragma unroll
    for (int mt = 0; mt < 2; ++mt) {
        const int rg = gt0 + mg + mt * 16 + frow;
#pragma unroll
        for (int nt = 0; nt < 8; ++nt) {
            const int gc = ng * 64 + nt * 8 + 2 * fcol;
            *(float2*)(out + rg * Hm + gc)       = make_float2(acc[mt][nt].x, acc[mt][nt].y);
            *(float2*)(out + (rg + 8) * Hm + gc) = make_float2(acc[mt][nt].z, acc[mt][nt].w);
        }
    }
}

// ============================================================
extern "C" void kernel_launch(void* const* d_in, const int* in_sizes, int n_in,
                              void* d_out, int out_size) {
    const int*   x      = (const int*)  d_in[0];
    const float* emb    = (const float*)d_in[1];
    const float* pos    = (const float*)d_in[2];
    const float* lw1    = (const float*)d_in[3];
    const float* lb1    = (const float*)d_in[4];
    const float* lw2    = (const float*)d_in[5];
    const float* lb2    = (const float*)d_in[6];
    const float* lln_g  = (const float*)d_in[7];
    const float* lln_b  = (const float*)d_in[8];
    const float* pool_w = (const float*)d_in[9];
    const float* pool_b = (const float*)d_in[10];
    const float* msg_w1 = (const float*)d_in[11];
    const float* msg_b1 = (const float*)d_in[12];
    const float* msg_w2 = (const float*)d_in[13];
    const float* msg_b2 = (const float*)d_in[14];
    const float* upd_w1 = (const float*)d_in[15];
    const float* upd_b1 = (const float*)d_in[16];
    const float* upd_w2 = (const float*)d_in[17];
    const float* upd_b2 = (const float*)d_in[18];
    const float* mln_g  = (const float*)d_in[19];
    const float* mln_b  = (const float*)d_in[20];
    const float* bc_w   = (const float*)d_in[21];
    const float* bc_b   = (const float*)d_in[22];
    const float* fln_g  = (const float*)d_in[23];
    const float* fln_b  = (const float*)d_in[24];
    const float* head_w = (const float*)d_in[25];
    float* out = (float*)d_out;

    const int SMEM_LOCAL = (128 * SXL + 128 * SHL) * 4;  // 200704 B
    const int SMEM_MSG   = 48 * 1024;
    cudaFuncSetAttribute(k_local, cudaFuncAttributeMaxDynamicSharedMemorySize, SMEM_LOCAL);
    cudaFuncSetAttribute(k_msg,   cudaFuncAttributeMaxDynamicSharedMemorySize, SMEM_MSG);

    // weight packing (tiny)
    float2* w1p; cudaGetSymbolAddress((void**)&w1p, g_w1p);
    float2* w2p; cudaGetSymbolAddress((void**)&w2p, g_w2p);
    float2* hwp; cudaGetSymbolAddress((void**)&hwp, g_hwp);
    k_pack<<<64, 256>>>(lw1, w1p, 128, 256);
    k_pack<<<64, 256>>>(lw2, w2p, 256, 128);
    k_pack<<<64, 256>>>(head_w, hwp, 128, 256);

    k_local<<<NTOK / 128, 512, SMEM_LOCAL>>>(x, emb, pos, lb1, lb2,
                                             lln_g, lln_b, pool_w, pool_b);

    // rounds: A->B, B->A, A->B  (final state in g_hB)
    for (int r = 0; r < 3; ++r) {
        const int useA = (r % 2 == 0) ? 1 : 0;
        k_msg<<<ROWS / 16, 256, SMEM_MSG>>>(useA, msg_w1, msg_b1, msg_w2, msg_b2,
                                            upd_w1, upd_b1, upd_w2, upd_b2, mln_g, mln_b);
    }

    k_bc<<<ROWS / 32, 256>>>(bc_w, bc_b);
    k_head<<<NTOK / 64, 256>>>(fln_g, fln_b, out);
}

// round 5
// speedup vs baseline: 2.8628x; 1.7095x over previous
#include <cuda_runtime.h>

#define Dm 128
#define Hm 256
#define ROWS 16384   /* 16 * 1024 chunks */
#define NTOK 131072  /* 16 * 8192 tokens */
#define EPSf 1e-5f

typedef unsigned long long u64;
typedef unsigned int u32;

// ---- scratch (device globals; no allocation) ----
__device__ float g_local[NTOK * Dm];   // 64 MB
__device__ float g_hA[ROWS * Dm];      // 8 MB
__device__ float g_hB[ROWS * Dm];      // 8 MB
__device__ float g_proj[ROWS * Hm];    // 16 MB [row][0:128]=self, [128:256]=nbr
__device__ float g_bcb[ROWS * Dm];     // 8 MB
// packed tf32 weight fragments
__device__ float2 g_w1p[16 * 32 * 32]; // lw1 128x256
__device__ float2 g_w2p[32 * 16 * 32]; // lw2 256x128
__device__ float2 g_hwp[16 * 32 * 32]; // head_w 128x256
// msg-path 128x128 matrices: [0]=w1self [1]=w1nbr [2]=mw2 [3]=uw1a [4]=uw1b [5]=uw2
__device__ float2 g_mwp[6 * 8192];

// ---- packed f32x2 helpers (scalar path) ----
__device__ __forceinline__ u64 pk2(float x, float y) {
    u64 r; asm("mov.b64 %0, {%1, %2};" : "=l"(r) : "f"(x), "f"(y)); return r;
}
__device__ __forceinline__ u64 dup_f(float a) {
    u64 r; asm("mov.b64 %0, {%1, %1};" : "=l"(r) : "f"(a)); return r;
}
__device__ __forceinline__ void fma2(u64& d, u64 a, u64 b) {
    asm("fma.rn.f32x2 %0, %1, %2, %0;" : "+l"(d) : "l"(a), "l"(b));
}
__device__ __forceinline__ float2 u2f(u64 v) {
    float2 r; asm("mov.b64 {%0, %1}, %2;" : "=f"(r.x), "=f"(r.y) : "l"(v)); return r;
}

// ---- tf32 helpers ----
__device__ __forceinline__ u32 f2tf(float f) {
    u32 r; asm("cvt.rna.tf32.f32 %0, %1;" : "=r"(r) : "f"(f)); return r;
}
__device__ __forceinline__ float f2tff(float f) { return __uint_as_float(f2tf(f)); }

// mma.sync m16n8k8 tf32
__device__ __forceinline__ void mma8(float4& c, const u32 a[4], u32 b0, u32 b1) {
    asm volatile(
        "mma.sync.aligned.m16n8k8.row.col.f32.tf32.tf32.f32 "
        "{%0,%1,%2,%3}, {%4,%5,%6,%7}, {%8,%9}, {%0,%1,%2,%3};"
        : "+f"(c.x), "+f"(c.y), "+f"(c.z), "+f"(c.w)
        : "r"(a[0]), "r"(a[1]), "r"(a[2]), "r"(a[3]), "r"(b0), "r"(b1));
}

// A-fragment loaders (frow = lane>>2, fcol = lane&3; ap pre-offset)
template<int STRIDE>
__device__ __forceinline__ void ldA_raw(const float* ap, u32 a[4]) {
    a[0] = __float_as_uint(ap[0]);
    a[1] = __float_as_uint(ap[8 * STRIDE]);
    a[2] = __float_as_uint(ap[4]);
    a[3] = __float_as_uint(ap[8 * STRIDE + 4]);
}
template<int STRIDE>
__device__ __forceinline__ void ldA_cvt(const float* ap, u32 a[4]) {
    a[0] = f2tf(ap[0]);
    a[1] = f2tf(ap[8 * STRIDE]);
    a[2] = f2tf(ap[4]);
    a[3] = f2tf(ap[8 * STRIDE + 4]);
}

__device__ __forceinline__ float wsum(float v) {
#pragma unroll
    for (int o = 16; o; o >>= 1) v += __shfl_xor_sync(0xffffffffu, v, o);
    return v;
}
__device__ __forceinline__ float gelu_f(float x) {
    return 0.5f * x * (1.0f + erff(x * 0.70710678118f));
}

// warp LayerNorm of a 128-wide row held as float4 per lane
__device__ __forceinline__ float4 ln_f4(float4 h, const float* __restrict__ g,
                                        const float* __restrict__ b, int lane) {
    const float mu = wsum(h.x + h.y + h.z + h.w) * (1.0f / 128.0f);
    const float a0 = h.x - mu, a1 = h.y - mu, a2 = h.z - mu, a3 = h.w - mu;
    const float var = wsum(a0 * a0 + a1 * a1 + a2 * a2 + a3 * a3) * (1.0f / 128.0f);
    const float rs = rsqrtf(var + EPSf);
    const int dd = lane * 4;
    const float4 gg = *(const float4*)(g + dd);
    const float4 bb = *(const float4*)(b + dd);
    return make_float4(a0 * rs * gg.x + bb.x, a1 * rs * gg.y + bb.y,
                       a2 * rs * gg.z + bb.z, a3 * rs * gg.w + bb.w);
}

// ---- scalar register-tiled GEMM accumulate (pool/bc only) ----
template<int KDIM, int RPT, int NCP>
__device__ __forceinline__ void mm_acc(const float* __restrict__ s,
                                       const float* __restrict__ W, const int ldw,
                                       u64 acc[RPT][NCP]) {
#pragma unroll 2
    for (int d = 0; d < KDIM; d += 2) {
        u64 w0[NCP], w1[NCP];
        if constexpr (NCP >= 2) {
#pragma unroll
            for (int c = 0; c < NCP; c += 2) {
                const ulonglong2 t0 = *(const ulonglong2*)(W + d * ldw + c * 2);
                const ulonglong2 t1 = *(const ulonglong2*)(W + (d + 1) * ldw + c * 2);
                w0[c] = t0.x; w0[c + 1] = t0.y;
                w1[c] = t1.x; w1[c + 1] = t1.y;
            }
        } else {
            w0[0] = *(const u64*)(W + d * ldw);
            w1[0] = *(const u64*)(W + (d + 1) * ldw);
        }
#pragma unroll
        for (int r = 0; r < RPT; ++r) {
            const float2 a = *(const float2*)(s + r * KDIM + d);
            const u64 a0 = dup_f(a.x), a1 = dup_f(a.y);
#pragma unroll
            for (int c = 0; c < NCP; ++c) {
                fma2(acc[r][c], a0, w0[c]);
                fma2(acc[r][c], a1, w1[c]);
            }
        }
    }
}

// ============================================================
// K0: pack W[K][N] row-major into tf32 B-fragment order
// ============================================================
__global__ __launch_bounds__(256) void k_pack(const float* __restrict__ W,
                                              float2* __restrict__ P,
                                              int K, int N) {
    const int idx = blockIdx.x * 256 + threadIdx.x;
    const int total = (K / 8) * (N / 8) * 32;
    if (idx >= total) return;
    const int lane = idx & 31;
    const int t = idx >> 5;
    const int nt = t % (N / 8);
    const int ks = t / (N / 8);
    const int k = ks * 8 + (lane & 3);
    const int n = nt * 8 + (lane >> 2);
    P[idx] = make_float2(f2tff(W[k * N + n]), f2tff(W[(k + 4) * N + n]));
}

// ============================================================
// K1: local = h + MLP2(LN(h)) + fused pool/summ (tensor-core)
// 64 tokens (=8 chunks)/block, 256 threads, ~98KB dyn smem
// ============================================================
#define SXL 132
#define SHL 260
__global__ __launch_bounds__(256) void k_local(
    const int* __restrict__ x, const float* __restrict__ emb, const float* __restrict__ pos,
    const float* __restrict__ lb1, const float* __restrict__ lb2,
    const float* __restrict__ lng, const float* __restrict__ lnb,
    const float* __restrict__ pw, const float* __restrict__ pb)
{
    extern __shared__ float sm[];
    float* s_x = sm;                // 64 x 132
    float* s_h = sm + 64 * SXL;     // 64 x 260
    const int tid = threadIdx.x, wid = tid >> 5, lane = tid & 31;
    const int gt0 = blockIdx.x * 64;
    const int frow = lane >> 2, fcol = lane & 3;

    // phase 1: LN per token -> tf32 in s_x
#pragma unroll
    for (int tt = 0; tt < 8; ++tt) {
        const int tl = wid * 8 + tt, gt = gt0 + tl;
        const int xt = __ldg(x + gt);
        const float4 e = *(const float4*)(emb + xt * Dm + lane * 4);
        const float4 p = *(const float4*)(pos + (gt & 7) * Dm + lane * 4);
        const float4 h = make_float4(e.x + p.x, e.y + p.y, e.z + p.z, e.w + p.w);
        const float4 v = ln_f4(h, lng, lnb, lane);
        float* dst = s_x + tl * SXL + lane * 4;
        dst[0] = f2tff(v.x); dst[1] = f2tff(v.y); dst[2] = f2tff(v.z); dst[3] = f2tff(v.w);
    }
    __syncthreads();

    const int mg = (wid >> 2) * 32;   // 2 m-groups of 32 rows
    const int ng = (wid & 3);         // 4 n-groups

    // phase 2: hid = gelu(xln @ lw1 + b1) -> tf32 in s_h (cols ng*64..+63)
    {
        float4 acc[2][8];
#pragma unroll
        for (int nt = 0; nt < 8; ++nt) {
            const int gc = ng * 64 + nt * 8 + 2 * fcol;
            const float b0 = lb1[gc], b1v = lb1[gc + 1];
#pragma unroll
            for (int mt = 0; mt < 2; ++mt) acc[mt][nt] = make_float4(b0, b1v, b0, b1v);
        }
#pragma unroll 4
        for (int ks = 0; ks < 16; ++ks) {
            u32 a[2][4];
#pragma unroll
            for (int mt = 0; mt < 2; ++mt)
                ldA_raw<SXL>(s_x + (mg + mt * 16 + frow) * SXL + ks * 8 + fcol, a[mt]);
#pragma unroll
            for (int nt = 0; nt < 8; ++nt) {
                const float2 b = g_w1p[(ks * 32 + ng * 8 + nt) * 32 + lane];
#pragma unroll
                for (int mt = 0; mt < 2; ++mt)
                    mma8(acc[mt][nt], a[mt], __float_as_uint(b.x), __float_as_uint(b.y));
            }
        }
#pragma unroll
        for (int mt = 0; mt < 2; ++mt) {
            const int rg = mg + mt * 16 + frow;
#pragma unroll
            for (int nt = 0; nt < 8; ++nt) {
                const int gc = ng * 64 + nt * 8 + 2 * fcol;
                *(float2*)(s_h + rg * SHL + gc) =
                    make_float2(f2tff(gelu_f(acc[mt][nt].x)), f2tff(gelu_f(acc[mt][nt].y)));
                *(float2*)(s_h + (rg + 8) * SHL + gc) =
                    make_float2(f2tff(gelu_f(acc[mt][nt].z)), f2tff(gelu_f(acc[mt][nt].w)));
            }
        }
    }
    __syncthreads();

    // phase 3: local = h + hid @ lw2 + b2 -> g_local and s_x (fp32)
    {
        float4 acc[2][4];
#pragma unroll
        for (int nt = 0; nt < 4; ++nt) {
            const int gc = ng * 32 + nt * 8 + 2 * fcol;
            const float b0 = lb2[gc], b1v = lb2[gc + 1];
#pragma unroll
            for (int mt = 0; mt < 2; ++mt) acc[mt][nt] = make_float4(b0, b1v, b0, b1v);
        }
#pragma unroll 4
        for (int ks = 0; ks < 32; ++ks) {
            u32 a[2][4];
#pragma unroll
            for (int mt = 0; mt < 2; ++mt)
                ldA_raw<SHL>(s_h + (mg + mt * 16 + frow) * SHL + ks * 8 + fcol, a[mt]);
#pragma unroll
            for (int nt = 0; nt < 4; ++nt) {
                const float2 b = g_w2p[(ks * 16 + ng * 4 + nt) * 32 + lane];
#pragma unroll
                for (int mt = 0; mt < 2; ++mt)
                    mma8(acc[mt][nt], a[mt], __float_as_uint(b.x), __float_as_uint(b.y));
            }
        }
#pragma unroll
        for (int mt = 0; mt < 2; ++mt) {
#pragma unroll
            for (int rr = 0; rr < 2; ++rr) {
                const int tl = mg + mt * 16 + frow + rr * 8;
                const int gt = gt0 + tl;
                const int xt = __ldg(x + gt);
#pragma unroll
                for (int nt = 0; nt < 4; ++nt) {
                    const int gc = ng * 32 + nt * 8 + 2 * fcol;
                    const float2 e = *(const float2*)(emb + xt * Dm + gc);
                    const float2 p = *(const float2*)(pos + (gt & 7) * Dm + gc);
                    const float cx = rr ? acc[mt][nt].z : acc[mt][nt].x;
                    const float cy = rr ? acc[mt][nt].w : acc[mt][nt].y;
                    const float2 o = make_float2(e.x + p.x + cx, e.y + p.y + cy);
                    *(float2*)(g_local + gt * Dm + gc) = o;
                    *(float2*)(s_x + tl * SXL + gc) = o;
                }
            }
        }
    }
    __syncthreads();

    // phase 4: chunk means (8 chunks) -> s_h[0:1024]
#pragma unroll
    for (int it = 0; it < 4; ++it) {
        const int idx = tid + it * 256;
        const int c = idx >> 7, dd = idx & 127;
        float s = 0.f;
#pragma unroll
        for (int t = 0; t < 8; ++t) s += s_x[(c * 8 + t) * SXL + dd];
        s_h[c * 128 + dd] = s * 0.125f;
    }
    __syncthreads();

    // phase 5: summ = mean @ pool_w + pool_b -> g_hA (warp per chunk)
    {
        const int j0 = lane * 4;
        u64 acc1[1][2];
        acc1[0][0] = pk2(pb[j0], pb[j0 + 1]);
        acc1[0][1] = pk2(pb[j0 + 2], pb[j0 + 3]);
        mm_acc<128, 1, 2>(s_h + wid * 128, pw + j0, 128, acc1);
        const float2 v0 = u2f(acc1[0][0]), v1 = u2f(acc1[0][1]);
        *(float4*)(g_hA + (blockIdx.x * 8 + wid) * Dm + j0) =
            make_float4(v0.x, v0.y, v1.x, v1.y);
    }
}

// ============================================================
// K2a: proj = [hmsg @ w1s | hmsg @ w1n] -> g_proj (tensor)
// 64 rows/block, grid 256, 256 threads
// ============================================================
__global__ __launch_bounds__(256) void k_mproj(int useA)
{
    const float* __restrict__ hin = useA ? g_hA : g_hB;
    __shared__ float s_in[64 * SXL];
    const int tid = threadIdx.x, wid = tid >> 5, lane = tid & 31;
    const int r0 = blockIdx.x * 64;
    const int frow = lane >> 2, fcol = lane & 3;

#pragma unroll
    for (int it = 0; it < 32; ++it) {
        const int idx = tid + it * 256;
        const int r = idx >> 7, dd = idx & 127;
        s_in[r * SXL + dd] = f2tff(hin[(r0 + r) * Dm + dd]);
    }
    __syncthreads();

    const int mg = (wid & 1) * 32;        // 2 m-groups of 32 rows
    const int grp = wid >> 1;             // 0..3
    const int mat = grp >> 1;             // 0=self, 1=nbr
    const int nh = grp & 1;               // col half (64 cols)
    const float2* __restrict__ WP = g_mwp + mat * 8192;

    float4 acc[2][8];
#pragma unroll
    for (int mt = 0; mt < 2; ++mt)
#pragma unroll
        for (int nt = 0; nt < 8; ++nt) acc[mt][nt] = make_float4(0.f, 0.f, 0.f, 0.f);

#pragma unroll 4
    for (int ks = 0; ks < 16; ++ks) {
        u32 a[2][4];
#pragma unroll
        for (int mt = 0; mt < 2; ++mt)
            ldA_raw<SXL>(s_in + (mg + mt * 16 + frow) * SXL + ks * 8 + fcol, a[mt]);
#pragma unroll
        for (int nt = 0; nt < 8; ++nt) {
            const float2 b = WP[(ks * 16 + nh * 8 + nt) * 32 + lane];
#pragma unroll
            for (int mt = 0; mt < 2; ++mt)
                mma8(acc[mt][nt], a[mt], __float_as_uint(b.x), __float_as_uint(b.y));
        }
    }

#pragma unroll
    for (int mt = 0; mt < 2; ++mt) {
        const int rg = r0 + mg + mt * 16 + frow;
#pragma unroll
        for (int nt = 0; nt < 8; ++nt) {
            const int gc = mat * 128 + nh * 64 + nt * 8 + 2 * fcol;
            *(float2*)(g_proj + rg * Hm + gc)       = make_float2(acc[mt][nt].x, acc[mt][nt].y);
            *(float2*)(g_proj + (rg + 8) * Hm + gc) = make_float2(acc[mt][nt].z, acc[mt][nt].w);
        }
    }
}

// ============================================================
// K2b: gelu-sum -> agg -> upd MLP -> LN (tensor)
// 64 rows/block, grid 256, 256 threads, ~99KB dyn smem
// ============================================================
__global__ __launch_bounds__(256) void k_msg2(
    int useA,
    const float* __restrict__ mb1, const float* __restrict__ mb2,
    const float* __restrict__ ub1, const float* __restrict__ ub2,
    const float* __restrict__ lg, const float* __restrict__ lb)
{
    const float* __restrict__ hin = useA ? g_hA : g_hB;
    float* __restrict__ hout = useA ? g_hB : g_hA;
    extern __shared__ float sm[];
    float* s_hm = sm;              // 64x132 fp32 hmsg
    float* s_hs = sm + 64 * SXL;   // 64x132 tf32 gelu-sum, later uh
    float* s_ag = sm + 128 * SXL;  // 64x132 tf32 agg, later fp32 pre-LN
    const int tid = threadIdx.x, wid = tid >> 5, lane = tid & 31;
    const int r0 = blockIdx.x * 64;
    const int frow = lane >> 2, fcol = lane & 3;

    // P0: load hmsg + gelu-sum from g_proj
#pragma unroll
    for (int it = 0; it < 32; ++it) {
        const int idx = tid + it * 256;
        const int r = idx >> 7, j = idx & 127;
        s_hm[r * SXL + j] = hin[(r0 + r) * Dm + j];
        const int row = r0 + r;
        const int i = row & 1023;
        const float ps_b = __ldg(g_proj + row * Hm + j) + mb1[j];
        float a = 0.f;
#pragma unroll
        for (int dd = 0; dd < 5; ++dd) {
            if (i >= dd) a += gelu_f(ps_b + __ldg(g_proj + (row - dd) * Hm + 128 + j));
        }
        s_hs[r * SXL + j] = f2tff(a);
    }
    __syncthreads();

    const int mg = (wid >> 2) * 32;
    const int ng = (wid & 3);

    // P1: agg = (HS @ mw2)/count + b2 -> s_ag (tf32)
    {
        float4 acc[2][4];
#pragma unroll
        for (int mt = 0; mt < 2; ++mt)
#pragma unroll
            for (int nt = 0; nt < 4; ++nt) acc[mt][nt] = make_float4(0.f, 0.f, 0.f, 0.f);
#pragma unroll 4
        for (int ks = 0; ks < 16; ++ks) {
            u32 a[2][4];
#pragma unroll
            for (int mt = 0; mt < 2; ++mt)
                ldA_raw<SXL>(s_hs + (mg + mt * 16 + frow) * SXL + ks * 8 + fcol, a[mt]);
#pragma unroll
            for (int nt = 0; nt < 4; ++nt) {
                const float2 b = g_mwp[2 * 8192 + (ks * 16 + ng * 4 + nt) * 32 + lane];
#pragma unroll
                for (int mt = 0; mt < 2; ++mt)
                    mma8(acc[mt][nt], a[mt], __float_as_uint(b.x), __float_as_uint(b.y));
            }
        }
        __syncthreads();
#pragma unroll
        for (int mt = 0; mt < 2; ++mt) {
            const int rA = mg + mt * 16 + frow;
            const int iA = (r0 + rA) & 1023, iB = (r0 + rA + 8) & 1023;
            const float invA = 1.0f / ((iA + 1) < 5 ? (float)(iA + 1) : 5.0f);
            const float invB = 1.0f / ((iB + 1) < 5 ? (float)(iB + 1) : 5.0f);
#pragma unroll
            for (int nt = 0; nt < 4; ++nt) {
                const int gc = ng * 32 + nt * 8 + 2 * fcol;
                const float b20 = mb2[gc], b21 = mb2[gc + 1];
                *(float2*)(s_ag + rA * SXL + gc) =
                    make_float2(f2tff(acc[mt][nt].x * invA + b20),
                                f2tff(acc[mt][nt].y * invA + b21));
                *(float2*)(s_ag + (rA + 8) * SXL + gc) =
                    make_float2(f2tff(acc[mt][nt].z * invB + b20),
                                f2tff(acc[mt][nt].w * invB + b21));
            }
        }
    }
    __syncthreads();

    // P2: uh = gelu(HM @ uw1a + AG @ uw1b + ub1) -> s_hs (tf32)
    {
        float4 acc[2][4];
#pragma unroll
        for (int nt = 0; nt < 4; ++nt) {
            const int gc = ng * 32 + nt * 8 + 2 * fcol;
            const float b0 = ub1[gc], b1v = ub1[gc + 1];
#pragma unroll
            for (int mt = 0; mt < 2; ++mt) acc[mt][nt] = make_float4(b0, b1v, b0, b1v);
        }
#pragma unroll 4
        for (int ks = 0; ks < 16; ++ks) {
            u32 a[2][4];
#pragma unroll
            for (int mt = 0; mt < 2; ++mt)
                ldA_cvt<SXL>(s_hm + (mg + mt * 16 + frow) * SXL + ks * 8 + fcol, a[mt]);
#pragma unroll
            for (int nt = 0; nt < 4; ++nt) {
                const float2 b = g_mwp[3 * 8192 + (ks * 16 + ng * 4 + nt) * 32 + lane];
#pragma unroll
                for (int mt = 0; mt < 2; ++mt)
                    mma8(acc[mt][nt], a[mt], __float_as_uint(b.x), __float_as_uint(b.y));
            }
        }
#pragma unroll 4
        for (int ks = 0; ks < 16; ++ks) {
            u32 a[2][4];
#pragma unroll
            for (int mt = 0; mt < 2; ++mt)
                ldA_raw<SXL>(s_ag + (mg + mt * 16 + frow) * SXL + ks * 8 + fcol, a[mt]);
#pragma unroll
            for (int nt = 0; nt < 4; ++nt) {
                const float2 b = g_mwp[4 * 8192 + (ks * 16 + ng * 4 + nt) * 32 + lane];
#pragma unroll
                for (int mt = 0; mt < 2; ++mt)
                    mma8(acc[mt][nt], a[mt], __float_as_uint(b.x), __float_as_uint(b.y));
            }
        }
        __syncthreads();
#pragma unroll
        for (int mt = 0; mt < 2; ++mt) {
            const int rA = mg + mt * 16 + frow;
#pragma unroll
            for (int nt = 0; nt < 4; ++nt) {
                const int gc = ng * 32 + nt * 8 + 2 * fcol;
                *(float2*)(s_hs + rA * SXL + gc) =
                    make_float2(f2tff(gelu_f(acc[mt][nt].x)), f2tff(gelu_f(acc[mt][nt].y)));
                *(float2*)(s_hs + (rA + 8) * SXL + gc) =
                    make_float2(f2tff(gelu_f(acc[mt][nt].z)), f2tff(gelu_f(acc[mt][nt].w)));
            }
        }
    }
    __syncthreads();

    // P3: pre-LN = hmsg + UH @ uw2 + ub2 -> s_ag (fp32)
    {
        float4 acc[2][4];
#pragma unroll
        for (int nt = 0; nt < 4; ++nt) {
            const int gc = ng * 32 + nt * 8 + 2 * fcol;
            const float b0 = ub2[gc], b1v = ub2[gc + 1];
#pragma unroll
            for (int mt = 0; mt < 2; ++mt) acc[mt][nt] = make_float4(b0, b1v, b0, b1v);
        }
#pragma unroll 4
        for (int ks = 0; ks < 16; ++ks) {
            u32 a[2][4];
#pragma unroll
            for (int mt = 0; mt < 2; ++mt)
                ldA_raw<SXL>(s_hs + (mg + mt * 16 + frow) * SXL + ks * 8 + fcol, a[mt]);
#pragma unroll
            for (int nt = 0; nt < 4; ++nt) {
                const float2 b = g_mwp[5 * 8192 + (ks * 16 + ng * 4 + nt) * 32 + lane];
#pragma unroll
                for (int mt = 0; mt < 2; ++mt)
                    mma8(acc[mt][nt], a[mt], __float_as_uint(b.x), __float_as_uint(b.y));
            }
        }
        __syncthreads();
#pragma unroll
        for (int mt = 0; mt < 2; ++mt) {
            const int rA = mg + mt * 16 + frow;
#pragma unroll
            for (int nt = 0; nt < 4; ++nt) {
                const int gc = ng * 32 + nt * 8 + 2 * fcol;
                const float2 h0 = *(const float2*)(s_hm + rA * SXL + gc);
                const float2 h1 = *(const float2*)(s_hm + (rA + 8) * SXL + gc);
                *(float2*)(s_ag + rA * SXL + gc) =
                    make_float2(h0.x + acc[mt][nt].x, h0.y + acc[mt][nt].y);
                *(float2*)(s_ag + (rA + 8) * SXL + gc) =
                    make_float2(h1.x + acc[mt][nt].z, h1.y + acc[mt][nt].w);
            }
        }
    }
    __syncthreads();

    // P4: LN per row -> hout
#pragma unroll
    for (int rr = 0; rr < 8; ++rr) {
        const int r = wid * 8 + rr;
        const float4 v = *(const float4*)(s_ag + r * SXL + lane * 4);
        *(float4*)(hout + (r0 + r) * Dm + lane * 4) = ln_f4(v, lg, lb, lane);
    }
}

// ============================================================
// K4: bc = hmsg_final @ bc_w + bc_b  (final state in g_hB)
// ============================================================
__global__ __launch_bounds__(256) void k_bc(
    const float* __restrict__ w, const float* __restrict__ b)
{
    __shared__ float s_r[32 * 128];
    const int tid = threadIdx.x;
    const int r0 = blockIdx.x * 32;
#pragma unroll
    for (int it = 0; it < 16; ++it) {
        const int idx = tid + it * 256;
        s_r[idx] = g_hB[r0 * Dm + idx];
    }
    __syncthreads();
    const int j0 = (tid & 31) * 4, rg = tid >> 5;
    u64 acc[4][2];
#pragma unroll
    for (int c = 0; c < 2; ++c) {
        const u64 bp = pk2(b[j0 + 2 * c], b[j0 + 2 * c + 1]);
#pragma unroll
        for (int r = 0; r < 4; ++r) acc[r][c] = bp;
    }
    mm_acc<128, 4, 2>(s_r + rg * 4 * 128, w + j0, 128, acc);
#pragma unroll
    for (int r = 0; r < 4; ++r) {
        const float2 v0 = u2f(acc[r][0]), v1 = u2f(acc[r][1]);
        *(float4*)(g_bcb + (r0 + rg * 4 + r) * Dm + j0) = make_float4(v0.x, v0.y, v1.x, v1.y);
    }
}

// ============================================================
// K5: logits = LN(local + bc) @ head_w (tensor), 64 tok/block
// ============================================================
__global__ __launch_bounds__(256) void k_head(
    const float* __restrict__ lg, const float* __restrict__ lb,
    float* __restrict__ out)
{
    __shared__ float s_x[64 * SXL];
    const int tid = threadIdx.x, wid = tid >> 5, lane = tid & 31;
    const int gt0 = blockIdx.x * 64;
    const int frow = lane >> 2, fcol = lane & 3;

#pragma unroll
    for (int tt = 0; tt < 8; ++tt) {
        const int tl = wid * 8 + tt, gt = gt0 + tl;
        const float4 lv = *(const float4*)(g_local + gt * Dm + lane * 4);
        const float4 bv = *(const float4*)(g_bcb + (gt >> 3) * Dm + lane * 4);
        const float4 h = make_float4(lv.x + bv.x, lv.y + bv.y, lv.z + bv.z, lv.w + bv.w);
        const float4 v = ln_f4(h, lg, lb, lane);
        float* dst = s_x + tl * SXL + lane * 4;
        dst[0] = f2tff(v.x); dst[1] = f2tff(v.y); dst[2] = f2tff(v.z); dst[3] = f2tff(v.w);
    }
    __syncthreads();

    const int mg = (wid >> 2) * 32;
    const int ng = (wid & 3);
    float4 acc[2][8];
#pragma unroll
    for (int mt = 0; mt < 2; ++mt)
#pragma unroll
        for (int nt = 0; nt < 8; ++nt) acc[mt][nt] = make_float4(0.f, 0.f, 0.f, 0.f);

#pragma unroll 4
    for (int ks = 0; ks < 16; ++ks) {
        u32 a[2][4];
#pragma unroll
        for (int mt = 0; mt < 2; ++mt)
            ldA_raw<SXL>(s_x + (mg + mt * 16 + frow) * SXL + ks * 8 + fcol, a[mt]);
#pragma unroll
        for (int nt = 0; nt < 8; ++nt) {
            const float2 b = g_hwp[(ks * 32 + ng * 8 + nt) * 32 + lane];
#pragma unroll
            for (int mt = 0; mt < 2; ++mt)
                mma8(acc[mt][nt], a[mt], __float_as_uint(b.x), __float_as_uint(b.y));
        }
    }

#pragma unroll
    for (int mt = 0; mt < 2; ++mt) {
        const int rg = gt0 + mg + mt * 16 + frow;
#pragma unroll
        for (int nt = 0; nt < 8; ++nt) {
            const int gc = ng * 64 + nt * 8 + 2 * fcol;
            *(float2*)(out + rg * Hm + gc)       = make_float2(acc[mt][nt].x, acc[mt][nt].y);
            *(float2*)(out + (rg + 8) * Hm + gc) = make_float2(acc[mt][nt].z, acc[mt][nt].w);
        }
    }
}

// ============================================================
extern "C" void kernel_launch(void* const* d_in, const int* in_sizes, int n_in,
                              void* d_out, int out_size) {
    const int*   x      = (const int*)  d_in[0];
    const float* emb    = (const float*)d_in[1];
    const float* pos    = (const float*)d_in[2];
    const float* lw1    = (const float*)d_in[3];
    const float* lb1    = (const float*)d_in[4];
    const float* lw2    = (const float*)d_in[5];
    const float* lb2    = (const float*)d_in[6];
    const float* lln_g  = (const float*)d_in[7];
    const float* lln_b  = (const float*)d_in[8];
    const float* pool_w = (const float*)d_in[9];
    const float* pool_b = (const float*)d_in[10];
    const float* msg_w1 = (const float*)d_in[11];
    const float* msg_b1 = (const float*)d_in[12];
    const float* msg_w2 = (const float*)d_in[13];
    const float* msg_b2 = (const float*)d_in[14];
    const float* upd_w1 = (const float*)d_in[15];
    const float* upd_b1 = (const float*)d_in[16];
    const float* upd_w2 = (const float*)d_in[17];
    const float* upd_b2 = (const float*)d_in[18];
    const float* mln_g  = (const float*)d_in[19];
    const float* mln_b  = (const float*)d_in[20];
    const float* bc_w   = (const float*)d_in[21];
    const float* bc_b   = (const float*)d_in[22];
    const float* fln_g  = (const float*)d_in[23];
    const float* fln_b  = (const float*)d_in[24];
    const float* head_w = (const float*)d_in[25];
    float* out = (float*)d_out;

    const int SMEM_LOCAL = (64 * SXL + 64 * SHL) * 4;   // 100352 B
    const int SMEM_MSG   = (192 * SXL) * 4;             // 101376 B
    cudaFuncSetAttribute(k_local, cudaFuncAttributeMaxDynamicSharedMemorySize, SMEM_LOCAL);
    cudaFuncSetAttribute(k_msg2,  cudaFuncAttributeMaxDynamicSharedMemorySize, SMEM_MSG);

    // weight packing (tiny)
    float2* w1p; cudaGetSymbolAddress((void**)&w1p, g_w1p);
    float2* w2p; cudaGetSymbolAddress((void**)&w2p, g_w2p);
    float2* hwp; cudaGetSymbolAddress((void**)&hwp, g_hwp);
    float2* mwp; cudaGetSymbolAddress((void**)&mwp, g_mwp);
    k_pack<<<64, 256>>>(lw1, w1p, 128, 256);
    k_pack<<<64, 256>>>(lw2, w2p, 256, 128);
    k_pack<<<64, 256>>>(head_w, hwp, 128, 256);
    k_pack<<<32, 256>>>(msg_w1,               mwp + 0 * 8192, 128, 128);
    k_pack<<<32, 256>>>(msg_w1 + 128 * 128,   mwp + 1 * 8192, 128, 128);
    k_pack<<<32, 256>>>(msg_w2,               mwp + 2 * 8192, 128, 128);
    k_pack<<<32, 256>>>(upd_w1,               mwp + 3 * 8192, 128, 128);
    k_pack<<<32, 256>>>(upd_w1 + 128 * 128,   mwp + 4 * 8192, 128, 128);
    k_pack<<<32, 256>>>(upd_w2,               mwp + 5 * 8192, 128, 128);

    k_local<<<NTOK / 64, 256, SMEM_LOCAL>>>(x, emb, pos, lb1, lb2,
                                            lln_g, lln_b, pool_w, pool_b);

    // rounds: A->B, B->A, A->B  (final state in g_hB)
    for (int r = 0; r < 3; ++r) {
        const int useA = (r % 2 == 0) ? 1 : 0;
        k_mproj<<<ROWS / 64, 256>>>(useA);
        k_msg2<<<ROWS / 64, 256, SMEM_MSG>>>(useA, msg_b1, msg_b2,
                                             upd_b1, upd_b2, mln_g, mln_b);
    }

    k_bc<<<ROWS / 32, 256>>>(bc_w, bc_b);
    k_head<<<NTOK / 64, 256>>>(fln_g, fln_b, out);
}